// round 4
// baseline (speedup 1.0000x reference)
#include <cuda_runtime.h>

#define N_REL   200
#define BATCH   16384
#define DIM     128
#define N_ENT   500000
#define TILE    8
#define NBLOCKS 296
#define MAX_TILES 4096

// Scratch (static __device__ globals — no allocation allowed)
__device__ int g_cnt[N_REL];
__device__ int g_list[N_REL * BATCH];
__device__ int g_is64;
__device__ int g_ntiles;
__device__ int g_tile_r[MAX_TILES];
__device__ int g_tile_s[MAX_TILES];

// ---- packed f32x2 helpers (FFMA2: 2 FLOP-pairs per issue slot) ----
__device__ __forceinline__ unsigned long long ffma2(unsigned long long a,
                                                    unsigned long long b,
                                                    unsigned long long c) {
    unsigned long long d;
    asm("fma.rn.f32x2 %0, %1, %2, %3;" : "=l"(d) : "l"(a), "l"(b), "l"(c));
    return d;
}
__device__ __forceinline__ unsigned long long mul2(unsigned long long a,
                                                   unsigned long long b) {
    unsigned long long d;
    asm("mul.rn.f32x2 %0, %1, %2;" : "=l"(d) : "l"(a), "l"(b));
    return d;
}
__device__ __forceinline__ unsigned long long dup2(float x) {
    unsigned long long d;
    unsigned int xi = __float_as_uint(x);
    asm("mov.b64 %0, {%1, %2};" : "=l"(d) : "r"(xi), "r"(xi));
    return d;
}

// Read data[elem] under either index dtype, with defensive clamping.
__device__ __forceinline__ int read_idx(const void* data, int elem, int is64, int limit) {
    long long v;
    if (is64) v = ((const long long*)data)[elem];
    else      v = ((const int*)data)[elem];
    if (v < 0) v = 0;
    if (v >= limit) v = limit - 1;
    return (int)v;
}

// Zero per-launch state, detect index dtype, zero output.
__global__ void init_kernel(const unsigned int* __restrict__ data_w, float* out) {
    int t = blockIdx.x * blockDim.x + threadIdx.x;
    if (t < N_REL) g_cnt[t] = 0;
    if (t == 0) {
        out[0] = 0.0f;
        unsigned int acc = 0;
        #pragma unroll
        for (int k = 0; k < 32; k++) acc |= data_w[2 * k + 1];
        g_is64 = (acc == 0) ? 1 : 0;   // true int64 (<2^31) => odd words all zero
    }
}

// Bucket batch elements by relation id.
__global__ void build_kernel(const void* __restrict__ data) {
    int b = blockIdx.x * blockDim.x + threadIdx.x;
    if (b < BATCH) {
        int r = read_idx(data, b * 5 + 2, g_is64, N_REL);
        int p = atomicAdd(&g_cnt[r], 1);
        g_list[r * BATCH + p] = b;
    }
}

// Flat tile list (prefix scan over per-relation tile counts).
__global__ void plan_kernel() {
    __shared__ int s_off[N_REL + 1];
    if (threadIdx.x == 0) {
        int acc = 0;
        for (int r = 0; r < N_REL; r++) {
            s_off[r] = acc;
            acc += (g_cnt[r] + TILE - 1) / TILE;
        }
        s_off[N_REL] = acc;
        g_ntiles = acc;
    }
    __syncthreads();
    for (int r = threadIdx.x; r < N_REL; r += blockDim.x) {
        int off = s_off[r];
        int nt  = (g_cnt[r] + TILE - 1) / TILE;
        for (int i = 0; i < nt; i++) {
            g_tile_r[off + i] = r;
            g_tile_s[off + i] = i * TILE;
        }
    }
}

// Persistent: 296 blocks, each owns a contiguous range of tiles (sorted by
// relation). Thread = (column j = tid&127, row-half = tid>>7); R column in
// 64 scalar regs. Per tile: gather 8 elements' h/t/ch/ct interleaved as
// (pos,neg) float2 pairs, packed f32x2 FMAs compute both bilinears at once.
__global__ __launch_bounds__(256, 2) void rescal_kernel(
    const void*  __restrict__ data,
    const float* __restrict__ ent,
    const float* __restrict__ rel,
    float*       __restrict__ out)
{
    __shared__ float2 sh_h[TILE][DIM];    // (h, ch) per (elem, k)
    __shared__ float2 sh_t[TILE][DIM];    // (t, ct) per (elem, k)
    __shared__ int    sh_ids[TILE][4];    // h,t,ch,ct entity ids
    __shared__ float  wsum[TILE][8];

    const int tid  = threadIdx.x;
    const int col  = tid & 127;
    const int rowh = tid >> 7;            // which 64-row half
    const int lane = tid & 31;
    const int wid  = tid >> 5;
    const int is64 = g_is64;
    const int nt   = g_ntiles;

    const int t0 = (int)((long long)blockIdx.x * nt / NBLOCKS);
    const int t1 = (int)((long long)(blockIdx.x + 1) * nt / NBLOCKS);

    float Rreg[64];
    int   cur_r = -1;
    float blockAcc = 0.0f;                // carried on warps 0 and 1

    for (int t = t0; t < t1; t++) {
        const int r   = g_tile_r[t];
        const int s0  = g_tile_s[t];
        const int cnt = g_cnt[r];
        int nvalid = cnt - s0;
        if (nvalid > TILE) nvalid = TILE;

        if (r != cur_r) {                 // reload R column (L2-resident)
            const float* Rp = rel + (size_t)r * (DIM * DIM)
                                  + (size_t)(rowh * 64) * DIM + col;
            #pragma unroll
            for (int k = 0; k < 64; k++) Rreg[k] = __ldg(Rp + (size_t)k * DIM);
            cur_r = r;
        }

        __syncthreads();                  // prior tile done with sh_* / wsum
        if (tid < TILE) {
            int e  = tid;
            int bb = g_list[r * BATCH + s0 + ((e < nvalid) ? e : 0)];
            sh_ids[e][0] = read_idx(data, bb * 5 + 0, is64, N_ENT);  // h
            sh_ids[e][1] = read_idx(data, bb * 5 + 1, is64, N_ENT);  // t
            sh_ids[e][2] = read_idx(data, bb * 5 + 3, is64, N_ENT);  // ch
            sh_ids[e][3] = read_idx(data, bb * 5 + 4, is64, N_ENT);  // ct
        }
        __syncthreads();

        // Gather 4096 floats, 16 independent loads per thread (MLP hides DRAM).
        #pragma unroll
        for (int i = 0; i < 16; i++) {
            int flat = i * 256 + tid;
            int e = flat >> 9;            // element
            int v = (flat >> 7) & 3;      // 0:h 1:t 2:ch 3:ct
            int k = flat & 127;
            float val = ent[(size_t)sh_ids[e][v] * DIM + k];
            if      (v == 0) sh_h[e][k].x = val;
            else if (v == 2) sh_h[e][k].y = val;
            else if (v == 1) sh_t[e][k].x = val;
            else             sh_t[e][k].y = val;
        }
        __syncthreads();

        // Packed bilinear: acc[e] = (sum_i h*R , sum_i ch*R) for column `col`.
        unsigned long long acc[TILE];
        #pragma unroll
        for (int e = 0; e < TILE; e++) acc[e] = 0ull;

        const int kb = rowh * 64;
        #pragma unroll 4
        for (int k = 0; k < 64; k += 2) {
            unsigned long long b0 = dup2(Rreg[k]);
            unsigned long long b1 = dup2(Rreg[k + 1]);
            #pragma unroll
            for (int e = 0; e < TILE; e++) {
                ulonglong2 hv = *reinterpret_cast<const ulonglong2*>(&sh_h[e][kb + k]);
                acc[e] = ffma2(hv.x, b0, acc[e]);
                acc[e] = ffma2(hv.y, b1, acc[e]);
            }
        }

        // contrib_e = accp * t[col] - accn * ct[col]
        float cvals[TILE];
        #pragma unroll
        for (int e = 0; e < TILE; e++) {
            unsigned long long tv =
                *reinterpret_cast<const unsigned long long*>(&sh_t[e][col]);
            unsigned long long p = mul2(acc[e], tv);
            float lo = __uint_as_float((unsigned int)p);
            float hi = __uint_as_float((unsigned int)(p >> 32));
            cvals[e] = lo - hi;
        }

        // Per-warp reduction for all 8 elements -> wsum[e][wid].
        #pragma unroll
        for (int e = 0; e < TILE; e++) {
            float c = cvals[e];
            #pragma unroll
            for (int o = 16; o; o >>= 1)
                c += __shfl_xor_sync(0xffffffffu, c, o);
            if (lane == 0) wsum[e][wid] = c;
        }
        __syncthreads();

        // Cross-warp combine: warps 0 and 1 cover all 8 elements
        // (8 lanes per element: e = wid*4 + lane>>3).
        if (wid < 2) {
            int e = wid * 4 + (lane >> 3);
            int w = lane & 7;
            float v = wsum[e][w];
            v += __shfl_xor_sync(0xffffffffu, v, 4);
            v += __shfl_xor_sync(0xffffffffu, v, 2);
            v += __shfl_xor_sync(0xffffffffu, v, 1);
            if (w == 0 && e < nvalid) {
                v += 1.0f;                           // + MARGIN
                if (v > 0.0f) blockAcc += v * (1.0f / BATCH);
            }
        }
    }

    // blockAcc is nonzero only on lanes 0,8,16,24 of warps 0 and 1.
    if (wid < 2) {
        blockAcc += __shfl_xor_sync(0xffffffffu, blockAcc, 16);
        blockAcc += __shfl_xor_sync(0xffffffffu, blockAcc, 8);
        if (lane == 0 && blockAcc != 0.0f) atomicAdd(out, blockAcc);
    }
}

extern "C" void kernel_launch(void* const* d_in, const int* in_sizes, int n_in,
                              void* d_out, int out_size) {
    const void*  data = d_in[0];
    const float* ent  = (const float*)d_in[1];
    const float* rel  = (const float*)d_in[2];
    float*       out  = (float*)d_out;

    init_kernel<<<1, 256>>>((const unsigned int*)data, out);
    build_kernel<<<(BATCH + 255) / 256, 256>>>(data);
    plan_kernel<<<1, 256>>>();
    rescal_kernel<<<NBLOCKS, 256>>>(data, ent, rel, out);
}

// round 5
// speedup vs baseline: 1.2758x; 1.2758x over previous
#include <cuda_runtime.h>

#define N_REL   200
#define BATCH   16384
#define DIM     128
#define N_ENT   500000
#define TILE    8
#define NBLOCKS 296
#define MAXT    16

// Scratch (static __device__ globals — no allocation allowed)
__device__ int g_cnt[N_REL];
__device__ int g_list[N_REL * BATCH];
__device__ int g_is64;

typedef unsigned long long ull;

// ---- packed f32x2 helpers (FFMA2: pos/neg bilinears share one issue slot) ----
__device__ __forceinline__ ull ffma2(ull a, ull b, ull c) {
    ull d;
    asm("fma.rn.f32x2 %0, %1, %2, %3;" : "=l"(d) : "l"(a), "l"(b), "l"(c));
    return d;
}
__device__ __forceinline__ ull mul2(ull a, ull b) {
    ull d;
    asm("mul.rn.f32x2 %0, %1, %2;" : "=l"(d) : "l"(a), "l"(b));
    return d;
}
__device__ __forceinline__ ull dup2(float x) {
    ull d; unsigned int xi = __float_as_uint(x);
    asm("mov.b64 %0, {%1, %2};" : "=l"(d) : "r"(xi), "r"(xi));
    return d;
}

// ---- cp.async helpers ----
__device__ __forceinline__ void cp4(void* dst, const void* src) {
    unsigned sa = (unsigned)__cvta_generic_to_shared(dst);
    asm volatile("cp.async.ca.shared.global [%0], [%1], 4;" :: "r"(sa), "l"(src));
}
__device__ __forceinline__ void cp_commit() {
    asm volatile("cp.async.commit_group;" ::: "memory");
}
__device__ __forceinline__ void cp_wait1() {
    asm volatile("cp.async.wait_group 1;" ::: "memory");
}
__device__ __forceinline__ void cp_wait0() {
    asm volatile("cp.async.wait_group 0;" ::: "memory");
}

// Read data[elem] under either index dtype, with defensive clamping.
__device__ __forceinline__ int read_idx(const void* data, int elem, int is64, int limit) {
    long long v;
    if (is64) v = ((const long long*)data)[elem];
    else      v = ((const int*)data)[elem];
    if (v < 0) v = 0;
    if (v >= limit) v = limit - 1;
    return (int)v;
}

// Zero per-launch state, detect index dtype, zero output.
__global__ void init_kernel(const unsigned int* __restrict__ data_w, float* out) {
    int t = blockIdx.x * blockDim.x + threadIdx.x;
    if (t < N_REL) g_cnt[t] = 0;
    if (t == 0) {
        out[0] = 0.0f;
        unsigned int acc = 0;
        #pragma unroll
        for (int k = 0; k < 32; k++) acc |= data_w[2 * k + 1];
        g_is64 = (acc == 0) ? 1 : 0;   // true int64 (<2^31) => odd words all zero
    }
}

// Bucket batch elements by relation id.
__global__ void build_kernel(const void* __restrict__ data) {
    int b = blockIdx.x * blockDim.x + threadIdx.x;
    if (b < BATCH) {
        int r = read_idx(data, b * 5 + 2, g_is64, N_REL);
        int p = atomicAdd(&g_cnt[r], 1);
        g_list[r * BATCH + p] = b;
    }
}

struct __align__(16) Buf {
    float2 h[TILE][DIM];   // (h, ch)
    float2 t[TILE][DIM];   // (t, ct)
};

// Issue the async gather for one tile into one buffer (16 cp.async/thread).
__device__ __forceinline__ void issue_gather(
    Buf* buf, const int (*ids)[4], const float* __restrict__ ent, int tid)
{
    #pragma unroll
    for (int i = 0; i < 16; i++) {
        int flat = i * 256 + tid;          // 0..4095
        int e = flat >> 9;                 // element 0..7
        int v = (flat >> 7) & 3;           // 0:h 1:t 2:ch 3:ct
        int k = flat & 127;
        const float* src = ent + (size_t)ids[e][v] * DIM + k;
        float2* base = (v == 0 || v == 2) ? &buf->h[e][k] : &buf->t[e][k];
        float*  dst  = (v == 0 || v == 1) ? &base->x : &base->y;
        cp4(dst, src);
    }
    cp_commit();
}

// Persistent: NBLOCKS blocks, tile list derived in-block (scan of g_cnt).
// Thread = (col = tid&127, row-half = tid>>7). R column in 64 regs.
// Double-buffered cp.async gather hides entity-fetch latency behind FFMA2.
__global__ __launch_bounds__(256, 2) void rescal_kernel(
    const void*  __restrict__ data,
    const float* __restrict__ ent,
    const float* __restrict__ rel,
    float*       __restrict__ out)
{
    __shared__ Buf   s_buf[2];
    __shared__ int   s_scan[256];
    __shared__ int   s_toff[N_REL + 1];
    __shared__ int   st_r[MAXT], st_s[MAXT], st_n[MAXT];
    __shared__ int   s_ids[MAXT][TILE][4];
    __shared__ float wsum[TILE][8];
    __shared__ float s_w1;

    const int tid  = threadIdx.x;
    const int col  = tid & 127;
    const int rowh = tid >> 7;
    const int lane = tid & 31;
    const int wid  = tid >> 5;
    const int is64 = g_is64;

    // ---- prologue: tile-offset scan (Hillis-Steele over 256 slots) ----
    int tc = (tid < N_REL) ? (g_cnt[tid] + TILE - 1) / TILE : 0;
    s_scan[tid] = tc;
    __syncthreads();
    #pragma unroll
    for (int o = 1; o < 256; o <<= 1) {
        int v = (tid >= o) ? s_scan[tid - o] : 0;
        __syncthreads();
        s_scan[tid] += v;
        __syncthreads();
    }
    const int nt = s_scan[255];
    if (tid < N_REL) s_toff[tid] = s_scan[tid] - tc;   // exclusive prefix
    if (tid == 0)    s_toff[N_REL] = nt;
    __syncthreads();

    const int t0  = (int)((long long)blockIdx.x * nt / NBLOCKS);
    const int t1  = (int)((long long)(blockIdx.x + 1) * nt / NBLOCKS);
    const int ntb = t1 - t0;

    // ---- per-tile metadata (binary search relation per tile) ----
    if (tid < ntb && tid < MAXT) {
        int t = t0 + tid;
        int lo = 0, hi = N_REL;
        while (hi - lo > 1) {
            int m = (lo + hi) >> 1;
            if (s_toff[m] <= t) lo = m; else hi = m;
        }
        int s0 = (t - s_toff[lo]) * TILE;
        int nv = g_cnt[lo] - s0;
        st_r[tid] = lo;
        st_s[tid] = s0;
        st_n[tid] = (nv > TILE) ? TILE : nv;
    }
    __syncthreads();

    // ---- prefetch all entity ids for this block's tiles ----
    if (tid < ntb * TILE) {
        int tt = tid >> 3, e = tid & 7;
        int nv = st_n[tt];
        int b  = g_list[st_r[tt] * BATCH + st_s[tt] + ((e < nv) ? e : 0)];
        s_ids[tt][e][0] = read_idx(data, b * 5 + 0, is64, N_ENT);  // h
        s_ids[tt][e][1] = read_idx(data, b * 5 + 1, is64, N_ENT);  // t
        s_ids[tt][e][2] = read_idx(data, b * 5 + 3, is64, N_ENT);  // ch
        s_ids[tt][e][3] = read_idx(data, b * 5 + 4, is64, N_ENT);  // ct
    }
    __syncthreads();

    float Rreg[64];
    int   cur_r = -1;
    float blockAcc = 0.0f;                 // carried on warps 0 and 1

    if (ntb > 0) issue_gather(&s_buf[0], s_ids[0], ent, tid);

    for (int j = 0; j < ntb; j++) {
        if (j + 1 < ntb)
            issue_gather(&s_buf[(j + 1) & 1], s_ids[j + 1], ent, tid);

        const int r = st_r[j];
        if (r != cur_r) {                  // reload R column (L2-resident)
            const float* Rp = rel + (size_t)r * (DIM * DIM)
                                  + (size_t)(rowh * 64) * DIM + col;
            #pragma unroll
            for (int k = 0; k < 64; k++) Rreg[k] = __ldg(Rp + (size_t)k * DIM);
            cur_r = r;
        }

        if (j + 1 < ntb) cp_wait1(); else cp_wait0();
        __syncthreads();                   // tile j's data visible to all

        const Buf* buf = &s_buf[j & 1];
        const int  nvalid = st_n[j];
        const int  kb = rowh * 64;

        ull acc[TILE];
        #pragma unroll
        for (int e = 0; e < TILE; e++) acc[e] = 0ull;

        #pragma unroll 4
        for (int k = 0; k < 64; k += 2) {
            ull b0 = dup2(Rreg[k]);
            ull b1 = dup2(Rreg[k + 1]);
            #pragma unroll
            for (int e = 0; e < TILE; e++) {
                ulonglong2 hv = *reinterpret_cast<const ulonglong2*>(&buf->h[e][kb + k]);
                acc[e] = ffma2(hv.x, b0, acc[e]);
                acc[e] = ffma2(hv.y, b1, acc[e]);
            }
        }

        // contrib_e = accp * t[col] - accn * ct[col], then per-warp reduce
        #pragma unroll
        for (int e = 0; e < TILE; e++) {
            ull tv = *reinterpret_cast<const ull*>(&buf->t[e][col]);
            ull p  = mul2(acc[e], tv);
            float c = __uint_as_float((unsigned int)p)
                    - __uint_as_float((unsigned int)(p >> 32));
            #pragma unroll
            for (int o = 16; o; o >>= 1)
                c += __shfl_xor_sync(0xffffffffu, c, o);
            if (lane == 0) wsum[e][wid] = c;
        }
        __syncthreads();                   // wsum ready; buf[(j+1)&1] free

        // Warps 0 and 1 cover all 8 elements (8 lanes per element).
        if (wid < 2) {
            int e = wid * 4 + (lane >> 3);
            int w = lane & 7;
            float v = wsum[e][w];
            v += __shfl_xor_sync(0xffffffffu, v, 4);
            v += __shfl_xor_sync(0xffffffffu, v, 2);
            v += __shfl_xor_sync(0xffffffffu, v, 1);
            if (w == 0 && e < nvalid) {
                v += 1.0f;                 // + MARGIN
                if (v > 0.0f) blockAcc += v * (1.0f / BATCH);
            }
        }
    }

    // One atomic per block.
    if (wid < 2) {
        blockAcc += __shfl_xor_sync(0xffffffffu, blockAcc, 16);
        blockAcc += __shfl_xor_sync(0xffffffffu, blockAcc, 8);
    }
    if (wid == 1 && lane == 0) s_w1 = blockAcc;
    __syncthreads();
    if (tid == 0) {
        float total = blockAcc + s_w1;
        if (total != 0.0f) atomicAdd(out, total);
    }
}

extern "C" void kernel_launch(void* const* d_in, const int* in_sizes, int n_in,
                              void* d_out, int out_size) {
    const void*  data = d_in[0];
    const float* ent  = (const float*)d_in[1];
    const float* rel  = (const float*)d_in[2];
    float*       out  = (float*)d_out;

    init_kernel<<<1, 256>>>((const unsigned int*)data, out);
    build_kernel<<<(BATCH + 255) / 256, 256>>>(data);
    rescal_kernel<<<NBLOCKS, 256>>>(data, ent, rel, out);
}